// round 8
// baseline (speedup 1.0000x reference)
#include <cuda_runtime.h>
#include <cuda_bf16.h>

#define NT 2000
#define NS 512
#define NH 64

// Output packing (concatenated flattened tuple, float32):
//   Q  : [NT, NS]        at 0
//   C  : [NT, NS]        at 1,024,000
//   S  : [NT, NS, NH]    at 2,048,000
//   H1 : [NT, NS, NH]    at 67,584,000
//   H2 : [NT, NS, NH]    at 133,120,000
//   Qs : [NT, NS, 3]     at 198,656,000
#define OFF_C   1024000
#define OFF_S   2048000
#define OFF_H1  67584000
#define OFF_H2  133120000
#define OFF_QS  198656000

__device__ __forceinline__ float sigmoidf(float x) {
    return 1.0f / (1.0f + expf(-x));
}

// Stage one 32-step chunk of forcings into smem as float4 (p, t, e, pad).
// tid 0..31 load P,T; tid 32..63 load E. Zero-fill past NT.
__device__ __forceinline__ void stage_chunk(float* fb, int buf, int t0, int tid,
                                            int site,
                                            const float* __restrict__ P,
                                            const float* __restrict__ T,
                                            const float* __restrict__ E)
{
    if (tid < 32) {
        const int t = t0 + tid;
        float pv = 0.f, tv = 0.f;
        if (t < NT) { pv = P[t * NS + site]; tv = T[t * NS + site]; }
        fb[((buf * 32) + tid) * 4 + 0] = pv;
        fb[((buf * 32) + tid) * 4 + 1] = tv;
    } else {
        const int i = tid - 32;
        const int t = t0 + i;
        float ev = 0.f;
        if (t < NT) ev = E[t * NS + site];
        fb[((buf * 32) + i) * 4 + 2] = ev;
    }
}

__global__ void __launch_bounds__(64)
soil_cq_kernel(const float* __restrict__ P, const float* __restrict__ T,
               const float* __restrict__ E,
               const float* __restrict__ w,  const float* __restrict__ wk1,
               const float* __restrict__ wk2, const float* __restrict__ we1,
               const float* __restrict__ we2, const float* __restrict__ wl,
               const float* __restrict__ wo,  const float* __restrict__ wc,
               float* __restrict__ out)
{
    const int tid  = threadIdx.x;      // 0..63
    const int lane = tid & 31;
    const int wrp  = tid >> 5;         // 0..1
    const int site = blockIdx.x;       // 0..511
    const int j    = tid;              // hidden unit, 1 per thread

    __shared__ float4 fbuf[2][32];     // double-buffered forcing chunks
    __shared__ float4 partial[2][2];   // [slot][warp] per-warp reduction partials
    __shared__ float  smred[2];        // softmax cross-warp sum

    float* fb = (float*)fbuf;

    // ---- per-unit parameter precompute ----
    const float ew   = expf(w[j]) + 1.0f;
    const float sk1  = sigmoidf(wk1[j]);
    const float sk2  = sigmoidf(wk2[j]);
    const float se1  = sigmoidf(we1[j]);
    const float se2  = sigmoidf(we2[j]);
    const float L    = expf(wl[j]);
    const float csk1 = 1.0f - sk1;          // h1a - q1 = h1a*csk1
    const float csk2 = 1.0f - 2.0f * sk2;   // h2a - 2*q2 = h2a*csk2

    // softmax(wo) over all 64 units (warp butterfly + smem cross-warp combine)
    const float ex = expf(wo[j]);
    float esum = ex;
    #pragma unroll
    for (int o = 16; o; o >>= 1) esum += __shfl_xor_sync(0xffffffffu, esum, o);
    if (lane == 0) smred[wrp] = esum;

    // overlap chunk-0 staging with the softmax barrier
    stage_chunk(fb, 0, 0, tid, site, P, T, E);
    __syncthreads();

    esum = smred[0] + smred[1];
    const float a  = ex / esum;
    const float ar = a / (sk2 * (1.0f + expf(wc[j])));

    // ---- state in registers ----
    float s = 0.f, h1 = 0.f, h2 = 0.f;

    // ---- output pointers ----
    float* Qp  = out + site;
    float* Cp  = out + OFF_C  + site;
    float* Sp  = out + OFF_S  + (size_t)site * NH + j;
    float* H1p = out + OFF_H1 + (size_t)site * NH + j;
    float* H2p = out + OFF_H2 + (size_t)site * NH + j;
    float* QSp = out + OFF_QS + (size_t)site * 3 + lane;   // lanes 0..2 of warp 0

    for (int t0 = 0; t0 < NT; t0 += 32) {
        const int buf = (t0 >> 5) & 1;
        // prefetch next chunk into the other buffer (consumed >=32 barriers later)
        stage_chunk(fb, buf ^ 1, t0 + 32, tid, site, P, T, E);

        int rem = NT - t0; if (rem > 32) rem = 32;

        #pragma unroll 4
        for (int i = 0; i < rem; ++i) {
            const float4 f = fbuf[buf][i];     // LDS.128 broadcast
            const float p = f.x, t = f.y, e = f.z;

            const float trel = fmaxf(t, 0.0f);
            const float ppos = (t > 0.0f) ? p : 0.0f;
            const float pneg = (t < 0.0f) ? p : 0.0f;

            // ---- snow + soil bucket, one unit per lane ----
            const float m   = fminf(trel * ew, s);
            s = s - m + pneg;
            const float x   = ppos + m;
            const float h1a = fmaxf(h1 + h2 + x - L, 0.0f);
            const float h2a = fminf(h1a + h2 + x, L);
            const float q1  = h1a * sk1;
            const float q2  = h2a * sk2;
            h1 = fmaxf(fmaf(h1a, csk1, -e * se1), 0.0f);
            h2 = fmaxf(fmaf(h2a, csk2, -e * se2), 0.0f);

            // ---- state stores (256B contiguous per block per array) ----
            *Sp  = s;
            *H1p = h1;
            *H2p = h2;
            Sp  += NS * NH;
            H1p += NS * NH;
            H2p += NS * NH;

            // ---- per-warp butterfly over 32 lanes ----
            float qa1 = q1 * a;
            float qa2 = q2 * a;
            float qc  = q2 * ar;
            #pragma unroll
            for (int o = 16; o; o >>= 1) {
                qa1 += __shfl_xor_sync(0xffffffffu, qa1, o);
                qa2 += __shfl_xor_sync(0xffffffffu, qa2, o);
                qc  += __shfl_xor_sync(0xffffffffu, qc,  o);
            }

            const int slot = i & 1;            // 2-slot ring, 1 barrier/iter apart
            if (lane == 0) partial[slot][wrp] = make_float4(qa1, qa2, qc, 0.f);
            __syncthreads();

            if (wrp == 0) {
                const float4 p0 = partial[slot][0];
                const float4 p1 = partial[slot][1];
                const float r1 = p0.x + p1.x;
                const float r2 = p0.y + p1.y;
                const float rc = p0.z + p1.z;
                const float Qk = r1 + r2;
                if (lane == 0) *Qp = Qk;
                if (lane == 1) *Cp = __fdividef(rc * (1.0f / 64.0f) + 1e-5f,
                                                Qk + 1e-5f);
                if (lane < 3)  *QSp = (lane == 0) ? r1 : ((lane == 1) ? r2 : 0.0f);
            }
            Qp  += NS;
            Cp  += NS;
            QSp += NS * 3;
        }
    }
}

extern "C" void kernel_launch(void* const* d_in, const int* in_sizes, int n_in,
                              void* d_out, int out_size)
{
    (void)in_sizes; (void)n_in; (void)out_size;
    soil_cq_kernel<<<NS, 64>>>(
        (const float*)d_in[0], (const float*)d_in[1], (const float*)d_in[2],
        (const float*)d_in[3], (const float*)d_in[4], (const float*)d_in[5],
        (const float*)d_in[6], (const float*)d_in[7], (const float*)d_in[8],
        (const float*)d_in[9], (const float*)d_in[10],
        (float*)d_out);
}

// round 9
// speedup vs baseline: 3.7915x; 3.7915x over previous
#include <cuda_runtime.h>
#include <cuda_bf16.h>

#define NT 2000
#define NS 512
#define NH 64

// Output packing (concatenated flattened tuple, float32):
//   Q  : [NT, NS]        at 0
//   C  : [NT, NS]        at 1,024,000
//   S  : [NT, NS, NH]    at 2,048,000
//   H1 : [NT, NS, NH]    at 67,584,000
//   H2 : [NT, NS, NH]    at 133,120,000
//   Qs : [NT, NS, 3]     at 198,656,000
#define OFF_C   1024000
#define OFF_S   2048000
#define OFF_H1  67584000
#define OFF_H2  133120000
#define OFF_QS  198656000

__device__ __forceinline__ float sigmoidf(float x) {
    return 1.0f / (1.0f + expf(-x));
}

__global__ void __launch_bounds__(32, 16)
soil_cq_kernel(const float* __restrict__ P, const float* __restrict__ T,
               const float* __restrict__ E,
               const float* __restrict__ w,  const float* __restrict__ wk1,
               const float* __restrict__ wk2, const float* __restrict__ we1,
               const float* __restrict__ we2, const float* __restrict__ wl,
               const float* __restrict__ wo,  const float* __restrict__ wc,
               float* __restrict__ out)
{
    const int lane = threadIdx.x;           // 0..31
    const int site = blockIdx.x;            // 0..511
    const int j0 = lane * 2;
    const int j1 = j0 + 1;

    // per-lane partial sums, [step][lane], padded to 33 for conflict-free
    // transposed reads in phase 2
    __shared__ float q1b[32][33];
    __shared__ float q2b[32][33];
    __shared__ float qcb[32][33];
    __shared__ float4 fbuf[2][32];          // forcing chunks (p,t,e,_)

    // ---- per-thread parameter precompute (2 hidden units per lane) ----
    const float ew0 = expf(w[j0]) + 1.0f,  ew1 = expf(w[j1]) + 1.0f;
    const float sk10 = sigmoidf(wk1[j0]),  sk11 = sigmoidf(wk1[j1]);
    const float sk20 = sigmoidf(wk2[j0]),  sk21 = sigmoidf(wk2[j1]);
    const float se10 = sigmoidf(we1[j0]),  se11 = sigmoidf(we1[j1]);
    const float se20 = sigmoidf(we2[j0]),  se21 = sigmoidf(we2[j1]);
    const float L0   = expf(wl[j0]),       L1   = expf(wl[j1]);
    const float csk10 = 1.0f - sk10,        csk11 = 1.0f - sk11;
    const float csk20 = 1.0f - 2.0f * sk20, csk21 = 1.0f - 2.0f * sk21;

    // softmax(wo) across the warp's 64 units
    float ex0 = expf(wo[j0]), ex1 = expf(wo[j1]);
    float esum = ex0 + ex1;
    #pragma unroll
    for (int o = 16; o; o >>= 1) esum += __shfl_xor_sync(0xffffffffu, esum, o);
    const float a0 = ex0 / esum, a1 = ex1 / esum;
    const float ar0 = a0 / (sk20 * (1.0f + expf(wc[j0])));
    const float ar1 = a1 / (sk21 * (1.0f + expf(wc[j1])));

    // ---- state in registers ----
    float s0 = 0.f, s1 = 0.f, h10 = 0.f, h11 = 0.f, h20 = 0.f, h21 = 0.f;

    // ---- state output pointers (coalesced float2 per warp) ----
    float* Sp  = out + OFF_S  + (size_t)site * NH + j0;
    float* H1p = out + OFF_H1 + (size_t)site * NH + j0;
    float* H2p = out + OFF_H2 + (size_t)site * NH + j0;

    // ---- stage chunk 0 forcings into smem ----
    {
        const float pv = P[lane * NS + site];
        const float tv = T[lane * NS + site];
        const float ev = E[lane * NS + site];
        fbuf[0][lane] = make_float4(pv, tv, ev, 0.f);
    }

    for (int t0 = 0; t0 < NT; t0 += 32) {
        const int buf = (t0 >> 5) & 1;
        const int rem = (NT - t0 < 32) ? (NT - t0) : 32;

        // prefetch next chunk's forcings into registers (LDG hidden under phase 1)
        float pN = 0.f, tN = 0.f, eN = 0.f;
        {
            const int tn = t0 + 32 + lane;
            if (tn < NT) {
                pN = P[tn * NS + site];
                tN = T[tn * NS + site];
                eN = E[tn * NS + site];
            }
        }

        __syncwarp();   // fbuf[buf] staged; previous phase 2 done reading q*b

        // ================= phase 1: recurrence, no shuffles =================
        #pragma unroll 8
        for (int i = 0; i < rem; ++i) {
            const float4 f = fbuf[buf][i];
            const float p = f.x, t = f.y, e = f.z;

            const float trel = fmaxf(t, 0.0f);
            const float ppos = (t > 0.0f) ? p : 0.0f;
            const float pneg = (t < 0.0f) ? p : 0.0f;
            const float es10 = e * se10, es11 = e * se11;
            const float es20 = e * se20, es21 = e * se21;

            // ---- unit 0 ----
            const float m0   = fminf(trel * ew0, s0);
            s0 = s0 - m0 + pneg;
            const float x0   = ppos + m0;
            const float h2x0 = h20 + x0;
            const float u0   = h10 + h2x0;
            const float h1a0 = fmaxf(u0 - L0, 0.0f);
            const float h2a0 = fminf(h1a0 + h2x0, L0);
            const float q10  = h1a0 * sk10;
            const float q20  = h2a0 * sk20;
            h10 = fmaxf(fmaf(h1a0, csk10, -es10), 0.0f);
            h20 = fmaxf(fmaf(h2a0, csk20, -es20), 0.0f);

            // ---- unit 1 ----
            const float m1   = fminf(trel * ew1, s1);
            s1 = s1 - m1 + pneg;
            const float x1   = ppos + m1;
            const float h2x1 = h21 + x1;
            const float u1   = h11 + h2x1;
            const float h1a1 = fmaxf(u1 - L1, 0.0f);
            const float h2a1 = fminf(h1a1 + h2x1, L1);
            const float q11  = h1a1 * sk11;
            const float q21  = h2a1 * sk21;
            h11 = fmaxf(fmaf(h1a1, csk11, -es11), 0.0f);
            h21 = fmaxf(fmaf(h2a1, csk21, -es21), 0.0f);

            // ---- coalesced state stores (256B/warp/array) ----
            *(float2*)Sp  = make_float2(s0,  s1);
            *(float2*)H1p = make_float2(h10, h11);
            *(float2*)H2p = make_float2(h20, h21);
            Sp  += NS * NH;
            H1p += NS * NH;
            H2p += NS * NH;

            // ---- stash per-lane partials (off critical path) ----
            q1b[i][lane] = q10 * a0  + q11 * a1;
            q2b[i][lane] = q20 * a0  + q21 * a1;
            qcb[i][lane] = q20 * ar0 + q21 * ar1;
        }

        // stage next chunk's forcings
        fbuf[buf ^ 1][lane] = make_float4(pN, tN, eN, 0.f);

        __syncwarp();   // q*b complete; fbuf[buf^1] staged

        // ========== phase 2: lane i reduces + emits outputs of step t0+i ==========
        if (lane < rem) {
            float a1a = 0.f, a1c = 0.f, a1e = 0.f, a1g = 0.f;
            float a2a = 0.f, a2c = 0.f, a2e = 0.f, a2g = 0.f;
            float aca = 0.f, acc = 0.f, ace = 0.f, acg = 0.f;
            const float* r1 = q1b[lane];
            const float* r2 = q2b[lane];
            const float* rc = qcb[lane];
            #pragma unroll
            for (int k = 0; k < 32; k += 4) {
                a1a += r1[k];     a2a += r2[k];     aca += rc[k];
                a1c += r1[k + 1]; a2c += r2[k + 1]; acc += rc[k + 1];
                a1e += r1[k + 2]; a2e += r2[k + 2]; ace += rc[k + 2];
                a1g += r1[k + 3]; a2g += r2[k + 3]; acg += rc[k + 3];
            }
            const float Qs1 = (a1a + a1c) + (a1e + a1g);
            const float Qs2 = (a2a + a2c) + (a2e + a2g);
            const float qcS = (aca + acc) + (ace + acg);
            const float Qk  = Qs1 + Qs2;
            const float c   = __fdividef(qcS * (1.0f / 64.0f) + 1e-5f, Qk + 1e-5f);

            const int t = t0 + lane;
            out[t * NS + site]         = Qk;
            out[OFF_C + t * NS + site] = c;
            float* qs = out + OFF_QS + ((size_t)t * NS + site) * 3;
            qs[0] = Qs1;
            qs[1] = Qs2;
            qs[2] = 0.0f;
        }
    }
}

extern "C" void kernel_launch(void* const* d_in, const int* in_sizes, int n_in,
                              void* d_out, int out_size)
{
    (void)in_sizes; (void)n_in; (void)out_size;
    soil_cq_kernel<<<NS, 32>>>(
        (const float*)d_in[0], (const float*)d_in[1], (const float*)d_in[2],
        (const float*)d_in[3], (const float*)d_in[4], (const float*)d_in[5],
        (const float*)d_in[6], (const float*)d_in[7], (const float*)d_in[8],
        (const float*)d_in[9], (const float*)d_in[10],
        (float*)d_out);
}